// round 1
// baseline (speedup 1.0000x reference)
#include <cuda_runtime.h>
#include <math.h>

#define B_  2
#define S_  2048
#define D_  768
#define H_  12
#define DK_ 64
#define M_  (B_*S_)   // 4096

// Scratch (allocation-free rule: __device__ globals)
__device__ float g_Q[B_*S_*D_];
__device__ float g_K[B_*S_*D_];
__device__ float g_V[B_*S_*D_];
__device__ float g_C[B_*S_*D_];

// ---------------------------------------------------------------------------
// GEMM: C[M,N] = A[M,K] @ W[K,N] + bias[N]   (all row-major, fp32)
// Tiles: BM=128, BN=64, BK=16; 256 threads; 8x4 register blocking per thread.
// ---------------------------------------------------------------------------
#define BM 128
#define BN 64
#define BK 16

__global__ __launch_bounds__(256) void gemm_bias_kernel(
    const float* __restrict__ A, const float* __restrict__ W,
    const float* __restrict__ bias, float* __restrict__ C,
    int M, int N, int K)
{
    __shared__ float As[BM][BK + 1];  // +1 pad: conflict-free column reads
    __shared__ float Ws[BK][BN];      // read via float4 -> conflict-free

    const int tid  = threadIdx.x;
    const int tx   = tid & 15;        // 0..15 (column group)
    const int ty   = tid >> 4;        // 0..15 (row group)
    const int row0 = blockIdx.y * BM;
    const int col0 = blockIdx.x * BN;

    float acc[8][4];
    #pragma unroll
    for (int i = 0; i < 8; i++)
        #pragma unroll
        for (int j = 0; j < 4; j++) acc[i][j] = 0.f;

    for (int k0 = 0; k0 < K; k0 += BK) {
        // Load A tile: 128x16 = 512 float4, 2 per thread
        #pragma unroll
        for (int i = 0; i < 2; i++) {
            int f4 = tid + i * 256;
            int r  = f4 >> 2;
            int c4 = f4 & 3;
            float4 v = *(const float4*)(A + (size_t)(row0 + r) * K + k0 + c4 * 4);
            As[r][c4*4+0] = v.x; As[r][c4*4+1] = v.y;
            As[r][c4*4+2] = v.z; As[r][c4*4+3] = v.w;
        }
        // Load W tile: 16x64 = 256 float4, 1 per thread
        {
            int r  = tid >> 4;
            int c4 = tid & 15;
            float4 v = *(const float4*)(W + (size_t)(k0 + r) * N + col0 + c4 * 4);
            *(float4*)&Ws[r][c4 * 4] = v;
        }
        __syncthreads();

        #pragma unroll
        for (int kk = 0; kk < BK; kk++) {
            float ra[8];
            #pragma unroll
            for (int i = 0; i < 8; i++) ra[i] = As[ty * 8 + i][kk];
            float4 rb = *(float4*)&Ws[kk][tx * 4];
            #pragma unroll
            for (int i = 0; i < 8; i++) {
                acc[i][0] += ra[i] * rb.x;
                acc[i][1] += ra[i] * rb.y;
                acc[i][2] += ra[i] * rb.z;
                acc[i][3] += ra[i] * rb.w;
            }
        }
        __syncthreads();
    }

    float4 bb = *(const float4*)(bias + col0 + tx * 4);
    #pragma unroll
    for (int i = 0; i < 8; i++) {
        float4 o;
        o.x = acc[i][0] + bb.x;
        o.y = acc[i][1] + bb.y;
        o.z = acc[i][2] + bb.z;
        o.w = acc[i][3] + bb.w;
        *(float4*)(C + (size_t)(row0 + ty * 8 + i) * N + col0 + tx * 4) = o;
    }
}

// ---------------------------------------------------------------------------
// Flash attention, fp32. One thread owns one query row (q + acc in registers).
// Block: 128 threads = 128 queries. KV tiles of 32 keys in shared memory.
// Grid: (S/128, H, B).
// ---------------------------------------------------------------------------
#define TQ 128
#define TK 32

__global__ __launch_bounds__(128) void attn_kernel(
    const float* __restrict__ Q, const float* __restrict__ K,
    const float* __restrict__ V, float* __restrict__ O)
{
    const int tid = threadIdx.x;
    const int h   = blockIdx.y;
    const int b   = blockIdx.z;
    const int qi  = blockIdx.x * TQ + tid;

    __shared__ float Ks[TK][DK_];
    __shared__ float Vs[TK][DK_];

    // Fold 1/sqrt(d_k) into q up front
    const float qscale = 0.125f;
    float q[DK_];
    {
        const float* qp = Q + ((size_t)(b * S_ + qi)) * D_ + h * DK_;
        #pragma unroll
        for (int d = 0; d < DK_; d += 4) {
            float4 v = *(const float4*)(qp + d);
            q[d]   = v.x * qscale;
            q[d+1] = v.y * qscale;
            q[d+2] = v.z * qscale;
            q[d+3] = v.w * qscale;
        }
    }

    float m = -1e30f, l = 0.f;
    float acc[DK_];
    #pragma unroll
    for (int d = 0; d < DK_; d++) acc[d] = 0.f;

    for (int t = 0; t < S_; t += TK) {
        // Load K/V tile: 32x64 = 512 float4 each; 4 float4 per thread per tile
        #pragma unroll
        for (int i = 0; i < 4; i++) {
            int f4 = tid + i * 128;
            int r  = f4 >> 4;
            int c4 = f4 & 15;
            size_t goff = ((size_t)(b * S_ + t + r)) * D_ + h * DK_ + c4 * 4;
            *(float4*)&Ks[r][c4 * 4] = *(const float4*)(K + goff);
            *(float4*)&Vs[r][c4 * 4] = *(const float4*)(V + goff);
        }
        __syncthreads();

        // Scores for this tile: s[j] = q . k_j  (4 independent chains for ILP)
        float s[TK];
        #pragma unroll
        for (int j = 0; j < TK; j += 4) {
            float a0 = 0.f, a1 = 0.f, a2 = 0.f, a3 = 0.f;
            #pragma unroll
            for (int d = 0; d < DK_; d += 4) {
                float4 k0 = *(float4*)&Ks[j + 0][d];
                float4 k1 = *(float4*)&Ks[j + 1][d];
                float4 k2 = *(float4*)&Ks[j + 2][d];
                float4 k3 = *(float4*)&Ks[j + 3][d];
                a0 += q[d]*k0.x + q[d+1]*k0.y + q[d+2]*k0.z + q[d+3]*k0.w;
                a1 += q[d]*k1.x + q[d+1]*k1.y + q[d+2]*k1.z + q[d+3]*k1.w;
                a2 += q[d]*k2.x + q[d+1]*k2.y + q[d+2]*k2.z + q[d+3]*k2.w;
                a3 += q[d]*k3.x + q[d+1]*k3.y + q[d+2]*k3.z + q[d+3]*k3.w;
            }
            s[j + 0] = a0; s[j + 1] = a1; s[j + 2] = a2; s[j + 3] = a3;
        }

        // Online softmax update
        float mt = m;
        #pragma unroll
        for (int j = 0; j < TK; j++) mt = fmaxf(mt, s[j]);
        float corr = __expf(m - mt);
        float lsum = 0.f;
        #pragma unroll
        for (int j = 0; j < TK; j++) {
            float p = __expf(s[j] - mt);
            s[j] = p;
            lsum += p;
        }
        l = l * corr + lsum;
        m = mt;
        #pragma unroll
        for (int d = 0; d < DK_; d++) acc[d] *= corr;

        // acc += P @ V_tile
        #pragma unroll 4
        for (int j = 0; j < TK; j++) {
            float p = s[j];
            #pragma unroll
            for (int d = 0; d < DK_; d += 4) {
                float4 v = *(float4*)&Vs[j][d];
                acc[d]     += p * v.x;
                acc[d + 1] += p * v.y;
                acc[d + 2] += p * v.z;
                acc[d + 3] += p * v.w;
            }
        }
        __syncthreads();
    }

    float inv = 1.f / l;
    float* op = O + ((size_t)(b * S_ + qi)) * D_ + h * DK_;
    #pragma unroll
    for (int d = 0; d < DK_; d += 4) {
        float4 o;
        o.x = acc[d]     * inv;
        o.y = acc[d + 1] * inv;
        o.z = acc[d + 2] * inv;
        o.w = acc[d + 3] * inv;
        *(float4*)(op + d) = o;
    }
}

// ---------------------------------------------------------------------------
extern "C" void kernel_launch(void* const* d_in, const int* in_sizes, int n_in,
                              void* d_out, int out_size)
{
    const float* query = (const float*)d_in[0];
    const float* key   = (const float*)d_in[1];
    const float* value = (const float*)d_in[2];
    const float* Wq    = (const float*)d_in[3];
    const float* bq    = (const float*)d_in[4];
    const float* Wk    = (const float*)d_in[5];
    const float* bk    = (const float*)d_in[6];
    const float* Wv    = (const float*)d_in[7];
    const float* bv    = (const float*)d_in[8];
    const float* Wo    = (const float*)d_in[9];
    const float* bo    = (const float*)d_in[10];
    float* out = (float*)d_out;

    float *pQ, *pK, *pV, *pC;
    cudaGetSymbolAddress((void**)&pQ, g_Q);
    cudaGetSymbolAddress((void**)&pK, g_K);
    cudaGetSymbolAddress((void**)&pV, g_V);
    cudaGetSymbolAddress((void**)&pC, g_C);

    dim3 gGemm(D_ / BN, M_ / BM);   // (12, 32)

    gemm_bias_kernel<<<gGemm, 256>>>(query, Wq, bq, pQ, M_, D_, D_);
    gemm_bias_kernel<<<gGemm, 256>>>(key,   Wk, bk, pK, M_, D_, D_);
    gemm_bias_kernel<<<gGemm, 256>>>(value, Wv, bv, pV, M_, D_, D_);

    attn_kernel<<<dim3(S_ / TQ, H_, B_), TQ>>>(pQ, pK, pV, pC);

    gemm_bias_kernel<<<gGemm, 256>>>(pC, Wo, bo, out, M_, D_, D_);
}

// round 2
// speedup vs baseline: 3.4840x; 3.4840x over previous
#include <cuda_runtime.h>
#include <cuda_bf16.h>
#include <math.h>
#include <stdint.h>

#define B_  2
#define S_  2048
#define D_  768
#define H_  12
#define DK_ 64
#define M_  (B_*S_)   // 4096

// ---------------- scratch (__device__ globals; allocation-free rule) --------
__device__ __nv_bfloat16 g_Ah[M_*D_], g_Al[M_*D_];      // GEMM A split (reused)
__device__ __nv_bfloat16 g_Wh[D_*D_], g_Wl[D_*D_];      // weight split (reused)
__device__ float g_Qf[M_*D_], g_Kf[M_*D_], g_Vf[M_*D_], g_Cf[M_*D_];
__device__ __nv_bfloat16 g_Qh[M_*D_], g_Ql[M_*D_];
__device__ __nv_bfloat16 g_Kh[M_*D_], g_Kl[M_*D_];
__device__ __nv_bfloat16 g_Vh[M_*D_], g_Vl[M_*D_];

// ---------------- PTX helpers ----------------------------------------------
__device__ __forceinline__ uint32_t smem_u32(const void* p) {
    return (uint32_t)__cvta_generic_to_shared(p);
}
__device__ __forceinline__ void ldsm_x4(uint32_t& r0, uint32_t& r1, uint32_t& r2, uint32_t& r3, uint32_t addr) {
    asm volatile("ldmatrix.sync.aligned.m8n8.x4.shared.b16 {%0,%1,%2,%3}, [%4];\n"
                 : "=r"(r0), "=r"(r1), "=r"(r2), "=r"(r3) : "r"(addr));
}
__device__ __forceinline__ void ldsm_x4t(uint32_t& r0, uint32_t& r1, uint32_t& r2, uint32_t& r3, uint32_t addr) {
    asm volatile("ldmatrix.sync.aligned.m8n8.x4.trans.shared.b16 {%0,%1,%2,%3}, [%4];\n"
                 : "=r"(r0), "=r"(r1), "=r"(r2), "=r"(r3) : "r"(addr));
}
__device__ __forceinline__ void ldsm_x4a(uint32_t a[4], uint32_t addr) {
    ldsm_x4(a[0], a[1], a[2], a[3], addr);
}
__device__ __forceinline__ void mma_bf16(float d[4], const uint32_t a[4], uint32_t b0, uint32_t b1) {
    asm volatile("mma.sync.aligned.m16n8k16.row.col.f32.bf16.bf16.f32 "
                 "{%0,%1,%2,%3}, {%4,%5,%6,%7}, {%8,%9}, {%0,%1,%2,%3};\n"
                 : "+f"(d[0]), "+f"(d[1]), "+f"(d[2]), "+f"(d[3])
                 : "r"(a[0]), "r"(a[1]), "r"(a[2]), "r"(a[3]), "r"(b0), "r"(b1));
}
// split x into (hi, lo) bf16, packed as bf16x2 pairs of (x0, x1)
__device__ __forceinline__ void split_pack(float x0, float x1, uint32_t& hi, uint32_t& lo) {
    __nv_bfloat162 h = __floats2bfloat162_rn(x0, x1);
    float h0 = __bfloat162float(h.x), h1 = __bfloat162float(h.y);
    __nv_bfloat162 l = __floats2bfloat162_rn(x0 - h0, x1 - h1);
    hi = *reinterpret_cast<uint32_t*>(&h);
    lo = *reinterpret_cast<uint32_t*>(&l);
}

// ---------------- split-convert kernel: fp32 -> (hi, lo) bf16 ---------------
__global__ __launch_bounds__(256) void split_kernel(
    const float* __restrict__ x, __nv_bfloat16* __restrict__ hi,
    __nv_bfloat16* __restrict__ lo, float scale, int n)
{
    int i = (blockIdx.x * 256 + threadIdx.x) * 4;
    if (i >= n) return;
    float4 v = *(const float4*)(x + i);
    uint32_t h01, h23, l01, l23;
    split_pack(v.x * scale, v.y * scale, h01, l01);
    split_pack(v.z * scale, v.w * scale, h23, l23);
    *(uint2*)(hi + i) = make_uint2(h01, h23);
    *(uint2*)(lo + i) = make_uint2(l01, l23);
}

// ---------------- GEMM: C[4096,768] = A[4096,768] @ W[768,768] + bias -------
// bf16 2-split x3 MMA. BM=128, BN=64, BK=32; 256 thr (8 warps, 4x2).
// SMEM row strides padded: A rows 40 bf16 (80B), B rows 72 bf16 (144B)
// -> conflict-free ldmatrix.
__global__ __launch_bounds__(256, 1) void gemm_kernel(
    const __nv_bfloat16* __restrict__ Ah, const __nv_bfloat16* __restrict__ Al,
    const __nv_bfloat16* __restrict__ Bh, const __nv_bfloat16* __restrict__ Bl,
    const float* __restrict__ bias, float* __restrict__ C)
{
    __shared__ __align__(16) __nv_bfloat16 sA[2][128 * 40];
    __shared__ __align__(16) __nv_bfloat16 sB[2][32 * 72];

    const int tid = threadIdx.x;
    const int lane = tid & 31, warp = tid >> 5;
    const int wm = warp & 3, wn = warp >> 2;
    const int row0 = blockIdx.y * 128, col0 = blockIdx.x * 64;

    float acc[2][4][4] = {};

    const uint32_t sA0 = smem_u32(sA[0]), sA1 = smem_u32(sA[1]);
    const uint32_t sB0 = smem_u32(sB[0]), sB1 = smem_u32(sB[1]);

    for (int k0 = 0; k0 < D_; k0 += 32) {
        // load A tiles (128x32 bf16 per split): 512 uint4 per split
        #pragma unroll
        for (int i = 0; i < 2; i++) {
            int flat = tid + i * 256;
            int r = flat >> 2, c = flat & 3;
            size_t g = (size_t)(row0 + r) * D_ + k0 + c * 8;
            *(uint4*)(sA[0] + r * 40 + c * 8) = *(const uint4*)(Ah + g);
            *(uint4*)(sA[1] + r * 40 + c * 8) = *(const uint4*)(Al + g);
        }
        // load B tiles (32x64 bf16 per split): 256 uint4 per split
        {
            int r = tid >> 3, c = tid & 7;
            size_t g = (size_t)(k0 + r) * D_ + col0 + c * 8;
            *(uint4*)(sB[0] + r * 72 + c * 8) = *(const uint4*)(Bh + g);
            *(uint4*)(sB[1] + r * 72 + c * 8) = *(const uint4*)(Bl + g);
        }
        __syncthreads();

        #pragma unroll
        for (int kk = 0; kk < 2; kk++) {
            uint32_t aF[2][2][4];
            #pragma unroll
            for (int mt = 0; mt < 2; mt++) {
                uint32_t off = (uint32_t)((wm * 32 + mt * 16 + (lane & 15)) * 80 + kk * 32 + (lane >> 4) * 16);
                ldsm_x4a(aF[0][mt], sA0 + off);
                ldsm_x4a(aF[1][mt], sA1 + off);
            }
            uint32_t bF[2][4][2];
            #pragma unroll
            for (int g = 0; g < 2; g++) {
                uint32_t off = (uint32_t)((kk * 16 + (lane & 15)) * 144 + (wn * 32 + g * 16) * 2 + (lane >> 4) * 16);
                uint32_t r0, r1, r2, r3;
                ldsm_x4t(r0, r1, r2, r3, sB0 + off);
                bF[0][2*g][0] = r0; bF[0][2*g][1] = r1; bF[0][2*g+1][0] = r2; bF[0][2*g+1][1] = r3;
                ldsm_x4t(r0, r1, r2, r3, sB1 + off);
                bF[1][2*g][0] = r0; bF[1][2*g][1] = r1; bF[1][2*g+1][0] = r2; bF[1][2*g+1][1] = r3;
            }
            #pragma unroll
            for (int mt = 0; mt < 2; mt++)
                #pragma unroll
                for (int nt = 0; nt < 4; nt++) {
                    mma_bf16(acc[mt][nt], aF[0][mt], bF[0][nt][0], bF[0][nt][1]);
                    mma_bf16(acc[mt][nt], aF[0][mt], bF[1][nt][0], bF[1][nt][1]);
                    mma_bf16(acc[mt][nt], aF[1][mt], bF[0][nt][0], bF[0][nt][1]);
                }
        }
        __syncthreads();
    }

    #pragma unroll
    for (int mt = 0; mt < 2; mt++)
        #pragma unroll
        for (int nt = 0; nt < 4; nt++) {
            int r = row0 + wm * 32 + mt * 16 + (lane >> 2);
            int c = col0 + wn * 32 + nt * 8 + (lane & 3) * 2;
            float b0 = bias[c], b1 = bias[c + 1];
            C[(size_t)r * D_ + c]           = acc[mt][nt][0] + b0;
            C[(size_t)r * D_ + c + 1]       = acc[mt][nt][1] + b1;
            C[(size_t)(r + 8) * D_ + c]     = acc[mt][nt][2] + b0;
            C[(size_t)(r + 8) * D_ + c + 1] = acc[mt][nt][3] + b1;
        }
}

// ---------------- Flash attention (bf16 2-split x3 MMA) ---------------------
// Block: 256 thr (8 warps x m16 = 128 queries). KV tiles of 64 keys.
// SMEM byte layout (36864 B):
//   Q phase:  Qh @0 [128][72], Ql @18432
//   KV phase: Kh @0, Kl @9216, Vh @18432, Vl @27648  (each [64][72] bf16)
__global__ __launch_bounds__(256, 1) void attn_kernel(
    const __nv_bfloat16* __restrict__ Qh, const __nv_bfloat16* __restrict__ Ql,
    const __nv_bfloat16* __restrict__ Kh, const __nv_bfloat16* __restrict__ Kl,
    const __nv_bfloat16* __restrict__ Vh, const __nv_bfloat16* __restrict__ Vl,
    float* __restrict__ O)
{
    __shared__ __align__(16) char smem[36864];

    const int tid = threadIdx.x;
    const int lane = tid & 31, w = tid >> 5;
    const int b = blockIdx.z, h = blockIdx.y;
    const int q0 = blockIdx.x * 128;
    const int headoff = h * DK_;
    const uint32_t sbase = smem_u32(smem);

    // ---- stage Q, load fragments (register-resident for whole kernel) ----
    #pragma unroll
    for (int i = 0; i < 4; i++) {
        int flat = tid + i * 256;                 // 1024 uint4 per split
        int r = flat >> 3, c = flat & 7;
        size_t g = (size_t)(b * S_ + q0 + r) * D_ + headoff + c * 8;
        *(uint4*)(smem + r * 144 + c * 16)         = *(const uint4*)(Qh + g);
        *(uint4*)(smem + 18432 + r * 144 + c * 16) = *(const uint4*)(Ql + g);
    }
    __syncthreads();
    uint32_t qF[2][4][4];
    #pragma unroll
    for (int kt = 0; kt < 4; kt++) {
        uint32_t off = (uint32_t)((w * 16 + (lane & 15)) * 144 + kt * 32 + (lane >> 4) * 16);
        ldsm_x4a(qF[0][kt], sbase + off);
        ldsm_x4a(qF[1][kt], sbase + 18432 + off);
    }
    __syncthreads();

    float Oacc[8][4] = {};
    float m0 = -1e30f, m1 = -1e30f, lsum0 = 0.f, lsum1 = 0.f;

    for (int t = 0; t < S_; t += 64) {
        // ---- load KV tile (4 matrices x 512 uint4) ----
        #pragma unroll
        for (int i = 0; i < 2; i++) {
            int flat = tid + i * 256;
            int r = flat >> 3, c = flat & 7;
            size_t g = (size_t)(b * S_ + t + r) * D_ + headoff + c * 8;
            *(uint4*)(smem + r * 144 + c * 16)         = *(const uint4*)(Kh + g);
            *(uint4*)(smem + 9216 + r * 144 + c * 16)  = *(const uint4*)(Kl + g);
            *(uint4*)(smem + 18432 + r * 144 + c * 16) = *(const uint4*)(Vh + g);
            *(uint4*)(smem + 27648 + r * 144 + c * 16) = *(const uint4*)(Vl + g);
        }
        __syncthreads();

        // ---- S = Q . K^T  (K row-major [key][d] == native col-major B) ----
        float sF[8][4] = {};
        #pragma unroll
        for (int kt = 0; kt < 4; kt++) {
            #pragma unroll
            for (int g = 0; g < 4; g++) {
                uint32_t off = (uint32_t)(((g << 4) + ((lane >> 4) << 3) + (lane & 7)) * 144
                                          + kt * 32 + ((lane >> 3) & 1) * 16);
                uint32_t bh0, bh1, bh2, bh3, bl0, bl1, bl2, bl3;
                ldsm_x4(bh0, bh1, bh2, bh3, sbase + off);
                ldsm_x4(bl0, bl1, bl2, bl3, sbase + 9216 + off);
                mma_bf16(sF[2*g],   qF[0][kt], bh0, bh1);
                mma_bf16(sF[2*g],   qF[0][kt], bl0, bl1);
                mma_bf16(sF[2*g],   qF[1][kt], bh0, bh1);
                mma_bf16(sF[2*g+1], qF[0][kt], bh2, bh3);
                mma_bf16(sF[2*g+1], qF[0][kt], bl2, bl3);
                mma_bf16(sF[2*g+1], qF[1][kt], bh2, bh3);
            }
        }

        // ---- online softmax (rows r=lane/4 via [0],[1]; r+8 via [2],[3]) ----
        float tm0 = -1e30f, tm1 = -1e30f;
        #pragma unroll
        for (int nt = 0; nt < 8; nt++) {
            tm0 = fmaxf(tm0, fmaxf(sF[nt][0], sF[nt][1]));
            tm1 = fmaxf(tm1, fmaxf(sF[nt][2], sF[nt][3]));
        }
        tm0 = fmaxf(tm0, __shfl_xor_sync(0xffffffffu, tm0, 1));
        tm0 = fmaxf(tm0, __shfl_xor_sync(0xffffffffu, tm0, 2));
        tm1 = fmaxf(tm1, __shfl_xor_sync(0xffffffffu, tm1, 1));
        tm1 = fmaxf(tm1, __shfl_xor_sync(0xffffffffu, tm1, 2));
        float mn0 = fmaxf(m0, tm0), mn1 = fmaxf(m1, tm1);
        float corr0 = __expf(m0 - mn0), corr1 = __expf(m1 - mn1);
        float rs0 = 0.f, rs1 = 0.f;
        #pragma unroll
        for (int nt = 0; nt < 8; nt++) {
            sF[nt][0] = __expf(sF[nt][0] - mn0);
            sF[nt][1] = __expf(sF[nt][1] - mn0);
            sF[nt][2] = __expf(sF[nt][2] - mn1);
            sF[nt][3] = __expf(sF[nt][3] - mn1);
            rs0 += sF[nt][0] + sF[nt][1];
            rs1 += sF[nt][2] + sF[nt][3];
        }
        rs0 += __shfl_xor_sync(0xffffffffu, rs0, 1);
        rs0 += __shfl_xor_sync(0xffffffffu, rs0, 2);
        rs1 += __shfl_xor_sync(0xffffffffu, rs1, 1);
        rs1 += __shfl_xor_sync(0xffffffffu, rs1, 2);
        lsum0 = lsum0 * corr0 + rs0;  m0 = mn0;
        lsum1 = lsum1 * corr1 + rs1;  m1 = mn1;
        #pragma unroll
        for (int nt = 0; nt < 8; nt++) {
            Oacc[nt][0] *= corr0; Oacc[nt][1] *= corr0;
            Oacc[nt][2] *= corr1; Oacc[nt][3] *= corr1;
        }

        // ---- O += P . V  (V row-major [key][d] -> ldmatrix.trans B) ----
        #pragma unroll
        for (int kt = 0; kt < 4; kt++) {
            uint32_t aH[4], aL[4];
            split_pack(sF[2*kt][0],   sF[2*kt][1],   aH[0], aL[0]);
            split_pack(sF[2*kt][2],   sF[2*kt][3],   aH[1], aL[1]);
            split_pack(sF[2*kt+1][0], sF[2*kt+1][1], aH[2], aL[2]);
            split_pack(sF[2*kt+1][2], sF[2*kt+1][3], aH[3], aL[3]);
            #pragma unroll
            for (int g = 0; g < 4; g++) {
                uint32_t off = (uint32_t)((kt * 16 + (lane & 15)) * 144 + g * 32 + (lane >> 4) * 16);
                uint32_t vh0, vh1, vh2, vh3, vl0, vl1, vl2, vl3;
                ldsm_x4t(vh0, vh1, vh2, vh3, sbase + 18432 + off);
                ldsm_x4t(vl0, vl1, vl2, vl3, sbase + 27648 + off);
                mma_bf16(Oacc[2*g],   aH, vh0, vh1);
                mma_bf16(Oacc[2*g],   aH, vl0, vl1);
                mma_bf16(Oacc[2*g],   aL, vh0, vh1);
                mma_bf16(Oacc[2*g+1], aH, vh2, vh3);
                mma_bf16(Oacc[2*g+1], aH, vl2, vl3);
                mma_bf16(Oacc[2*g+1], aL, vh2, vh3);
            }
        }
        __syncthreads();
    }

    const float inv0 = 1.f / lsum0, inv1 = 1.f / lsum1;
    const int r = q0 + w * 16 + (lane >> 2);
    #pragma unroll
    for (int nt = 0; nt < 8; nt++) {
        int c = headoff + nt * 8 + (lane & 3) * 2;
        size_t o0 = (size_t)(b * S_ + r) * D_ + c;
        O[o0]     = Oacc[nt][0] * inv0;
        O[o0 + 1] = Oacc[nt][1] * inv0;
        size_t o1 = o0 + (size_t)8 * D_;
        O[o1]     = Oacc[nt][2] * inv1;
        O[o1 + 1] = Oacc[nt][3] * inv1;
    }
}

// ---------------------------------------------------------------------------
extern "C" void kernel_launch(void* const* d_in, const int* in_sizes, int n_in,
                              void* d_out, int out_size)
{
    const float* query = (const float*)d_in[0];
    const float* key   = (const float*)d_in[1];
    const float* value = (const float*)d_in[2];
    const float* Wq    = (const float*)d_in[3];
    const float* bq    = (const float*)d_in[4];
    const float* Wk    = (const float*)d_in[5];
    const float* bk    = (const float*)d_in[6];
    const float* Wv    = (const float*)d_in[7];
    const float* bv    = (const float*)d_in[8];
    const float* Wo    = (const float*)d_in[9];
    const float* bo    = (const float*)d_in[10];
    float* out = (float*)d_out;

    __nv_bfloat16 *pAh, *pAl, *pWh, *pWl, *pQh, *pQl, *pKh, *pKl, *pVh, *pVl;
    float *pQf, *pKf, *pVf, *pCf;
    cudaGetSymbolAddress((void**)&pAh, g_Ah);  cudaGetSymbolAddress((void**)&pAl, g_Al);
    cudaGetSymbolAddress((void**)&pWh, g_Wh);  cudaGetSymbolAddress((void**)&pWl, g_Wl);
    cudaGetSymbolAddress((void**)&pQf, g_Qf);  cudaGetSymbolAddress((void**)&pKf, g_Kf);
    cudaGetSymbolAddress((void**)&pVf, g_Vf);  cudaGetSymbolAddress((void**)&pCf, g_Cf);
    cudaGetSymbolAddress((void**)&pQh, g_Qh);  cudaGetSymbolAddress((void**)&pQl, g_Ql);
    cudaGetSymbolAddress((void**)&pKh, g_Kh);  cudaGetSymbolAddress((void**)&pKl, g_Kl);
    cudaGetSymbolAddress((void**)&pVh, g_Vh);  cudaGetSymbolAddress((void**)&pVl, g_Vl);

    const int nAct = M_ * D_;          // 3145728
    const int nW   = D_ * D_;          // 589824
    const int gAct = nAct / 4 / 256;   // 3072
    const int gW   = nW / 4 / 256;     // 576
    dim3 gGemm(D_ / 64, M_ / 128);     // (12, 32)

    // Q projection
    split_kernel<<<gAct, 256>>>(query, pAh, pAl, 1.f, nAct);
    split_kernel<<<gW,   256>>>(Wq,    pWh, pWl, 1.f, nW);
    gemm_kernel<<<gGemm, 256>>>(pAh, pAl, pWh, pWl, bq, pQf);
    // K projection
    split_kernel<<<gAct, 256>>>(key,   pAh, pAl, 1.f, nAct);
    split_kernel<<<gW,   256>>>(Wk,    pWh, pWl, 1.f, nW);
    gemm_kernel<<<gGemm, 256>>>(pAh, pAl, pWh, pWl, bk, pKf);
    // V projection
    split_kernel<<<gAct, 256>>>(value, pAh, pAl, 1.f, nAct);
    split_kernel<<<gW,   256>>>(Wv,    pWh, pWl, 1.f, nW);
    gemm_kernel<<<gGemm, 256>>>(pAh, pAl, pWh, pWl, bv, pVf);

    // split Q (fold 1/sqrt(64)=0.125), K, V for attention
    split_kernel<<<gAct, 256>>>(pQf, pQh, pQl, 0.125f, nAct);
    split_kernel<<<gAct, 256>>>(pKf, pKh, pKl, 1.f, nAct);
    split_kernel<<<gAct, 256>>>(pVf, pVh, pVl, 1.f, nAct);

    attn_kernel<<<dim3(S_ / 128, H_, B_), 256>>>(pQh, pQl, pKh, pKl, pVh, pVl, pCf);

    // output projection
    split_kernel<<<gAct, 256>>>(pCf, pAh, pAl, 1.f, nAct);
    split_kernel<<<gW,   256>>>(Wo,  pWh, pWl, 1.f, nW);
    gemm_kernel<<<gGemm, 256>>>(pAh, pAl, pWh, pWl, bo, out);
}

// round 4
// speedup vs baseline: 4.1379x; 1.1877x over previous
#include <cuda_runtime.h>
#include <cuda_bf16.h>
#include <math.h>
#include <stdint.h>

#define B_  2
#define S_  2048
#define D_  768
#define H_  12
#define DK_ 64
#define M_  (B_*S_)   // 4096

// ---------------- scratch (__device__ globals; allocation-free rule) --------
__device__ __nv_bfloat16 g_Ah[M_*D_], g_Al[M_*D_];   // activation split (also attn out)
__device__ __nv_bfloat16 g_Wh[D_*D_], g_Wl[D_*D_];   // weight split (reused)
__device__ __nv_bfloat16 g_Qh[M_*D_], g_Ql[M_*D_];
__device__ __nv_bfloat16 g_Kh[M_*D_], g_Kl[M_*D_];
__device__ __nv_bfloat16 g_Vh[M_*D_], g_Vl[M_*D_];

// ---------------- helpers ---------------------------------------------------
__device__ __forceinline__ uint32_t smem_u32(const void* p) {
    return (uint32_t)__cvta_generic_to_shared(p);
}
__device__ __forceinline__ void split_pack(float x0, float x1, uint32_t& hi, uint32_t& lo) {
    __nv_bfloat162 h = __floats2bfloat162_rn(x0, x1);
    float h0 = __bfloat162float(h.x), h1 = __bfloat162float(h.y);
    __nv_bfloat162 l = __floats2bfloat162_rn(x0 - h0, x1 - h1);
    hi = *reinterpret_cast<uint32_t*>(&h);
    lo = *reinterpret_cast<uint32_t*>(&l);
}
__device__ __forceinline__ void cp16(uint32_t dst, const void* src) {
    asm volatile("cp.async.cg.shared.global [%0], [%1], 16;\n" :: "r"(dst), "l"(src));
}
#define CP_COMMIT() asm volatile("cp.async.commit_group;\n" ::: "memory")
#define CP_WAIT0()  asm volatile("cp.async.wait_group 0;\n" ::: "memory")
#define CP_WAIT1()  asm volatile("cp.async.wait_group 1;\n" ::: "memory")

__device__ __forceinline__ void ldsm_x4(uint32_t& r0, uint32_t& r1, uint32_t& r2, uint32_t& r3, uint32_t addr) {
    asm volatile("ldmatrix.sync.aligned.m8n8.x4.shared.b16 {%0,%1,%2,%3}, [%4];\n"
                 : "=r"(r0), "=r"(r1), "=r"(r2), "=r"(r3) : "r"(addr));
}
__device__ __forceinline__ void ldsm_x4t(uint32_t& r0, uint32_t& r1, uint32_t& r2, uint32_t& r3, uint32_t addr) {
    asm volatile("ldmatrix.sync.aligned.m8n8.x4.trans.shared.b16 {%0,%1,%2,%3}, [%4];\n"
                 : "=r"(r0), "=r"(r1), "=r"(r2), "=r"(r3) : "r"(addr));
}
__device__ __forceinline__ void ldsm_x4a(uint32_t a[4], uint32_t addr) {
    ldsm_x4(a[0], a[1], a[2], a[3], addr);
}
__device__ __forceinline__ void mma_bf16(float d[4], const uint32_t a[4], uint32_t b0, uint32_t b1) {
    asm volatile("mma.sync.aligned.m16n8k16.row.col.f32.bf16.bf16.f32 "
                 "{%0,%1,%2,%3}, {%4,%5,%6,%7}, {%8,%9}, {%0,%1,%2,%3};\n"
                 : "+f"(d[0]), "+f"(d[1]), "+f"(d[2]), "+f"(d[3])
                 : "r"(a[0]), "r"(a[1]), "r"(a[2]), "r"(a[3]), "r"(b0), "r"(b1));
}

// ---------------- input split: fp32 -> (hi, lo) bf16 ------------------------
__global__ __launch_bounds__(256) void split_kernel(
    const float* __restrict__ x, __nv_bfloat16* __restrict__ hi,
    __nv_bfloat16* __restrict__ lo, int n)
{
    int i = (blockIdx.x * 256 + threadIdx.x) * 4;
    if (i >= n) return;
    float4 v = *(const float4*)(x + i);
    uint32_t h01, h23, l01, l23;
    split_pack(v.x, v.y, h01, l01);
    split_pack(v.z, v.w, h23, l23);
    *(uint2*)(hi + i) = make_uint2(h01, h23);
    *(uint2*)(lo + i) = make_uint2(l01, l23);
}

// ---------------- GEMM: C[4096,768] = A @ W + bias --------------------------
// bf16 3-term split HMMA. BM=128 BN=64 BK=32; 256 thr (8 warps, 4x2).
// cp.async double-buffered. Epilogue: fp32 (mode 0) or split bf16 (mode 1).
// Stage layout (29696 B): Ah@0 (80B rows), Al@10240, Bh@20480 (144B rows), Bl@25088
#define GA_H 0u
#define GA_L 10240u
#define GB_H 20480u
#define GB_L 25088u
#define GSTAGE 29696u
#define GSMEM (2 * GSTAGE)

__global__ __launch_bounds__(256) void gemm_kernel(
    const __nv_bfloat16* __restrict__ Ah, const __nv_bfloat16* __restrict__ Al,
    const __nv_bfloat16* __restrict__ Wh, const __nv_bfloat16* __restrict__ Wl,
    const float* __restrict__ bias,
    float* __restrict__ outF, __nv_bfloat16* __restrict__ outH,
    __nv_bfloat16* __restrict__ outL, float scale, int mode)
{
    extern __shared__ char sm[];
    const int tid = threadIdx.x;
    const int lane = tid & 31, warp = tid >> 5;
    const int wm = warp & 3, wn = warp >> 2;
    const int row0 = blockIdx.y * 128, col0 = blockIdx.x * 64;
    const uint32_t sbase = smem_u32(sm);

    float acc[2][4][4] = {};

    auto load_stage = [&](int stage, int k0) {
        uint32_t st = sbase + stage * GSTAGE;
        #pragma unroll
        for (int i = 0; i < 2; i++) {
            int f = tid + i * 256;
            int r = f >> 2, c = f & 3;
            size_t g = (size_t)(row0 + r) * D_ + k0 + c * 8;
            cp16(st + GA_H + r * 80 + c * 16, Ah + g);
            cp16(st + GA_L + r * 80 + c * 16, Al + g);
        }
        {
            int r = tid >> 3, c = tid & 7;
            size_t g = (size_t)(k0 + r) * D_ + col0 + c * 8;
            cp16(st + GB_H + r * 144 + c * 16, Wh + g);
            cp16(st + GB_L + r * 144 + c * 16, Wl + g);
        }
        CP_COMMIT();
    };

    load_stage(0, 0);

    const int NCHUNK = D_ / 32;   // 24
    for (int chunk = 0; chunk < NCHUNK; chunk++) {
        if (chunk + 1 < NCHUNK) {
            load_stage((chunk + 1) & 1, (chunk + 1) * 32);
            CP_WAIT1();
        } else {
            CP_WAIT0();
        }
        __syncthreads();
        const uint32_t st = sbase + (chunk & 1) * GSTAGE;

        #pragma unroll
        for (int kk = 0; kk < 2; kk++) {
            uint32_t aF[2][2][4];
            #pragma unroll
            for (int mt = 0; mt < 2; mt++) {
                uint32_t off = (uint32_t)((wm * 32 + mt * 16 + (lane & 15)) * 80 + kk * 32 + (lane >> 4) * 16);
                ldsm_x4a(aF[0][mt], st + GA_H + off);
                ldsm_x4a(aF[1][mt], st + GA_L + off);
            }
            uint32_t bF[2][4][2];
            #pragma unroll
            for (int g = 0; g < 2; g++) {
                uint32_t off = (uint32_t)((kk * 16 + (lane & 15)) * 144 + (wn * 32 + g * 16) * 2 + (lane >> 4) * 16);
                uint32_t r0, r1, r2, r3;
                ldsm_x4t(r0, r1, r2, r3, st + GB_H + off);
                bF[0][2*g][0] = r0; bF[0][2*g][1] = r1; bF[0][2*g+1][0] = r2; bF[0][2*g+1][1] = r3;
                ldsm_x4t(r0, r1, r2, r3, st + GB_L + off);
                bF[1][2*g][0] = r0; bF[1][2*g][1] = r1; bF[1][2*g+1][0] = r2; bF[1][2*g+1][1] = r3;
            }
            #pragma unroll
            for (int mt = 0; mt < 2; mt++)
                #pragma unroll
                for (int nt = 0; nt < 4; nt++) {
                    mma_bf16(acc[mt][nt], aF[0][mt], bF[0][nt][0], bF[0][nt][1]);
                    mma_bf16(acc[mt][nt], aF[0][mt], bF[1][nt][0], bF[1][nt][1]);
                    mma_bf16(acc[mt][nt], aF[1][mt], bF[0][nt][0], bF[0][nt][1]);
                }
        }
        __syncthreads();
    }

    #pragma unroll
    for (int mt = 0; mt < 2; mt++)
        #pragma unroll
        for (int nt = 0; nt < 4; nt++) {
            int r = row0 + wm * 32 + mt * 16 + (lane >> 2);
            int c = col0 + wn * 32 + nt * 8 + (lane & 3) * 2;
            float b0 = bias[c], b1 = bias[c + 1];
            if (mode == 0) {
                outF[(size_t)r * D_ + c]           = acc[mt][nt][0] + b0;
                outF[(size_t)r * D_ + c + 1]       = acc[mt][nt][1] + b1;
                outF[(size_t)(r + 8) * D_ + c]     = acc[mt][nt][2] + b0;
                outF[(size_t)(r + 8) * D_ + c + 1] = acc[mt][nt][3] + b1;
            } else {
                uint32_t hh, ll;
                split_pack((acc[mt][nt][0] + b0) * scale, (acc[mt][nt][1] + b1) * scale, hh, ll);
                *(uint32_t*)(outH + (size_t)r * D_ + c) = hh;
                *(uint32_t*)(outL + (size_t)r * D_ + c) = ll;
                split_pack((acc[mt][nt][2] + b0) * scale, (acc[mt][nt][3] + b1) * scale, hh, ll);
                *(uint32_t*)(outH + (size_t)(r + 8) * D_ + c) = hh;
                *(uint32_t*)(outL + (size_t)(r + 8) * D_ + c) = ll;
            }
        }
}

// ---------------- Flash attention (bf16 2-split x3 HMMA, cp.async pipe) -----
// Block: 256 thr (8 warps x m16 = 128 queries). KV tiles of 64 keys,
// double-buffered. Stage (36864 B): Kh@0 Kl@9216 Vh@18432 Vl@27648, 144B rows.
// Q staged once in buffer 0. Output: split bf16 (for O-projection).
#define AK_H 0u
#define AK_L 9216u
#define AV_H 18432u
#define AV_L 27648u
#define ASTAGE 36864u
#define ASMEM (2 * ASTAGE)

__global__ __launch_bounds__(256, 1) void attn_kernel(
    const __nv_bfloat16* __restrict__ Qh, const __nv_bfloat16* __restrict__ Ql,
    const __nv_bfloat16* __restrict__ Kh, const __nv_bfloat16* __restrict__ Kl,
    const __nv_bfloat16* __restrict__ Vh, const __nv_bfloat16* __restrict__ Vl,
    __nv_bfloat16* __restrict__ Oh, __nv_bfloat16* __restrict__ Ol)
{
    extern __shared__ char smem[];
    const int tid = threadIdx.x;
    const int lane = tid & 31, w = tid >> 5;
    const int b = blockIdx.z, h = blockIdx.y;
    const int q0 = blockIdx.x * 128;
    const int headoff = h * DK_;
    const uint32_t sbase = smem_u32(smem);

    auto load_kv = [&](int stage, int t) {
        uint32_t st = sbase + stage * ASTAGE;
        #pragma unroll
        for (int i = 0; i < 2; i++) {
            int flat = tid + i * 256;
            int r = flat >> 3, c = flat & 7;
            size_t g = (size_t)(b * S_ + t + r) * D_ + headoff + c * 8;
            uint32_t o = (uint32_t)(r * 144 + c * 16);
            cp16(st + AK_H + o, Kh + g);
            cp16(st + AK_L + o, Kl + g);
            cp16(st + AV_H + o, Vh + g);
            cp16(st + AV_L + o, Vl + g);
        }
        CP_COMMIT();
    };

    // stage Q into buffer 0 (Qh@0, Ql@18432), prefetch KV tile 0 into buffer 1
    #pragma unroll
    for (int i = 0; i < 4; i++) {
        int flat = tid + i * 256;
        int r = flat >> 3, c = flat & 7;
        size_t g = (size_t)(b * S_ + q0 + r) * D_ + headoff + c * 8;
        uint32_t o = (uint32_t)(r * 144 + c * 16);
        cp16(sbase + o, Qh + g);
        cp16(sbase + 18432 + o, Ql + g);
    }
    CP_COMMIT();
    load_kv(1, 0);
    CP_WAIT1();           // Q group complete (KV tile 0 may still be in flight)
    __syncthreads();

    uint32_t qF[2][4][4];
    #pragma unroll
    for (int kt = 0; kt < 4; kt++) {
        uint32_t off = (uint32_t)((w * 16 + (lane & 15)) * 144 + kt * 32 + (lane >> 4) * 16);
        ldsm_x4a(qF[0][kt], sbase + off);
        ldsm_x4a(qF[1][kt], sbase + 18432 + off);
    }
    __syncthreads();      // Q fragments consumed; buffer 0 free for KV tile 1

    float Oacc[8][4] = {};
    float m0 = -1e30f, m1 = -1e30f, lsum0 = 0.f, lsum1 = 0.f;

    const int NT = S_ / 64;   // 32 tiles; tile ti lives in buffer (ti+1)&1
    for (int ti = 0; ti < NT; ti++) {
        if (ti + 1 < NT) {
            load_kv(ti & 1, (ti + 1) * 64);
            CP_WAIT1();
        } else {
            CP_WAIT0();
        }
        __syncthreads();
        const uint32_t cur = sbase + ((ti + 1) & 1) * ASTAGE;

        // ---- S = Q . K^T ----
        float sF[8][4] = {};
        #pragma unroll
        for (int kt = 0; kt < 4; kt++) {
            #pragma unroll
            for (int g = 0; g < 4; g++) {
                uint32_t off = (uint32_t)(((g << 4) + ((lane >> 4) << 3) + (lane & 7)) * 144
                                          + kt * 32 + ((lane >> 3) & 1) * 16);
                uint32_t bh0, bh1, bh2, bh3, bl0, bl1, bl2, bl3;
                ldsm_x4(bh0, bh1, bh2, bh3, cur + AK_H + off);
                ldsm_x4(bl0, bl1, bl2, bl3, cur + AK_L + off);
                mma_bf16(sF[2*g],   qF[0][kt], bh0, bh1);
                mma_bf16(sF[2*g],   qF[0][kt], bl0, bl1);
                mma_bf16(sF[2*g],   qF[1][kt], bh0, bh1);
                mma_bf16(sF[2*g+1], qF[0][kt], bh2, bh3);
                mma_bf16(sF[2*g+1], qF[0][kt], bl2, bl3);
                mma_bf16(sF[2*g+1], qF[1][kt], bh2, bh3);
            }
        }

        // ---- online softmax ----
        float tm0 = -1e30f, tm1 = -1e30f;
        #pragma unroll
        for (int nt = 0; nt < 8; nt++) {
            tm0 = fmaxf(tm0, fmaxf(sF[nt][0], sF[nt][1]));
            tm1 = fmaxf(tm1, fmaxf(sF[nt][2], sF[nt][3]));
        }
        tm0 = fmaxf(tm0, __shfl_xor_sync(0xffffffffu, tm0, 1));
        tm0 = fmaxf(tm0, __shfl_xor_sync(0xffffffffu, tm0, 2));
        tm1 = fmaxf(tm1, __shfl_xor_sync(0xffffffffu, tm1, 1));
        tm1 = fmaxf(tm1, __shfl_xor_sync(0xffffffffu, tm1, 2));
        float mn0 = fmaxf(m0, tm0), mn1 = fmaxf(m1, tm1);
        float corr0 = __expf(m0 - mn0), corr1 = __expf(m1 - mn1);
        float rs0 = 0.f, rs1 = 0.f;
        #pragma unroll
        for (int nt = 0; nt < 8; nt++) {
            sF[nt][0] = __expf(sF[nt][0] - mn0);
            sF[nt][1] = __expf(sF[nt][1] - mn0);
            sF[nt][2] = __expf(sF[nt][2] - mn1);
            sF[nt][3] = __expf(sF[nt][3] - mn1);
            rs0 += sF[nt][0] + sF[nt][1];
            rs1 += sF[nt][2] + sF[nt][3];
        }
        rs0 += __shfl_xor_sync(0xffffffffu, rs0, 1);
        rs0 += __shfl_xor_sync(0xffffffffu, rs0, 2);
        rs1 += __shfl_xor_sync(0xffffffffu, rs1, 1);
        rs1 += __shfl_xor_sync(0xffffffffu, rs1, 2);
        lsum0 = lsum0 * corr0 + rs0;  m0 = mn0;
        lsum1 = lsum1 * corr1 + rs1;  m1 = mn1;
        #pragma unroll
        for (int nt = 0; nt < 8; nt++) {
            Oacc[nt][0] *= corr0; Oacc[nt][1] *= corr0;
            Oacc[nt][2] *= corr1; Oacc[nt][3] *= corr1;
        }

        // ---- O += P . V ----
        #pragma unroll
        for (int kt = 0; kt < 4; kt++) {
            uint32_t aH[4], aL[4];
            split_pack(sF[2*kt][0],   sF[2*kt][1],   aH[0], aL[0]);
            split_pack(sF[2*kt][2],   sF[2*kt][3],   aH[1], aL[1]);
            split_pack(sF[2*kt+1][0], sF[2*kt+1][1], aH[2], aL[2]);
            split_pack(sF[2*kt+1][2], sF[2*kt+1][3], aH[3], aL[3]);
            #pragma unroll
            for (int g = 0; g < 4; g++) {
                uint32_t off = (uint32_t)((kt * 16 + (lane & 15)) * 144 + g * 32 + (lane >> 4) * 16);
                uint32_t vh0, vh1, vh2, vh3, vl0, vl1, vl2, vl3;
                ldsm_x4t(vh0, vh1, vh2, vh3, cur + AV_H + off);
                ldsm_x4t(vl0, vl1, vl2, vl3, cur + AV_L + off);
                mma_bf16(Oacc[2*g],   aH, vh0, vh1);
                mma_bf16(Oacc[2*g],   aH, vl0, vl1);
                mma_bf16(Oacc[2*g],   aL, vh0, vh1);
                mma_bf16(Oacc[2*g+1], aH, vh2, vh3);
                mma_bf16(Oacc[2*g+1], aH, vl2, vl3);
                mma_bf16(Oacc[2*g+1], aL, vh2, vh3);
            }
        }
        __syncthreads();
    }

    const float inv0 = 1.f / lsum0, inv1 = 1.f / lsum1;
    const int r = q0 + w * 16 + (lane >> 2);
    #pragma unroll
    for (int nt = 0; nt < 8; nt++) {
        int c = headoff + nt * 8 + (lane & 3) * 2;
        size_t o0 = (size_t)(b * S_ + r) * D_ + c;
        size_t o1 = o0 + (size_t)8 * D_;
        uint32_t hh, ll;
        split_pack(Oacc[nt][0] * inv0, Oacc[nt][1] * inv0, hh, ll);
        *(uint32_t*)(Oh + o0) = hh;
        *(uint32_t*)(Ol + o0) = ll;
        split_pack(Oacc[nt][2] * inv1, Oacc[nt][3] * inv1, hh, ll);
        *(uint32_t*)(Oh + o1) = hh;
        *(uint32_t*)(Ol + o1) = ll;
    }
}

// ---------------------------------------------------------------------------
extern "C" void kernel_launch(void* const* d_in, const int* in_sizes, int n_in,
                              void* d_out, int out_size)
{
    const float* query = (const float*)d_in[0];
    const float* key   = (const float*)d_in[1];
    const float* value = (const float*)d_in[2];
    const float* Wq    = (const float*)d_in[3];
    const float* bq    = (const float*)d_in[4];
    const float* Wk    = (const float*)d_in[5];
    const float* bk    = (const float*)d_in[6];
    const float* Wv    = (const float*)d_in[7];
    const float* bv    = (const float*)d_in[8];
    const float* Wo    = (const float*)d_in[9];
    const float* bo    = (const float*)d_in[10];
    float* out = (float*)d_out;

    __nv_bfloat16 *pAh, *pAl, *pWh, *pWl, *pQh, *pQl, *pKh, *pKl, *pVh, *pVl;
    cudaGetSymbolAddress((void**)&pAh, g_Ah);  cudaGetSymbolAddress((void**)&pAl, g_Al);
    cudaGetSymbolAddress((void**)&pWh, g_Wh);  cudaGetSymbolAddress((void**)&pWl, g_Wl);
    cudaGetSymbolAddress((void**)&pQh, g_Qh);  cudaGetSymbolAddress((void**)&pQl, g_Ql);
    cudaGetSymbolAddress((void**)&pKh, g_Kh);  cudaGetSymbolAddress((void**)&pKl, g_Kl);
    cudaGetSymbolAddress((void**)&pVh, g_Vh);  cudaGetSymbolAddress((void**)&pVl, g_Vl);

    cudaFuncSetAttribute(gemm_kernel, cudaFuncAttributeMaxDynamicSharedMemorySize, GSMEM);
    cudaFuncSetAttribute(attn_kernel, cudaFuncAttributeMaxDynamicSharedMemorySize, ASMEM);

    const int nAct = M_ * D_;          // 3145728
    const int nW   = D_ * D_;          // 589824
    const int gAct = nAct / 4 / 256;   // 3072
    const int gW   = nW / 4 / 256;     // 576
    dim3 gGemm(D_ / 64, M_ / 128);     // (12, 32)

    // Q projection (0.125 folded into split epilogue)
    split_kernel<<<gAct, 256>>>(query, pAh, pAl, nAct);
    split_kernel<<<gW,   256>>>(Wq, pWh, pWl, nW);
    gemm_kernel<<<gGemm, 256, GSMEM>>>(pAh, pAl, pWh, pWl, bq, nullptr, pQh, pQl, 0.125f, 1);
    // K projection
    split_kernel<<<gAct, 256>>>(key, pAh, pAl, nAct);
    split_kernel<<<gW,   256>>>(Wk, pWh, pWl, nW);
    gemm_kernel<<<gGemm, 256, GSMEM>>>(pAh, pAl, pWh, pWl, bk, nullptr, pKh, pKl, 1.f, 1);
    // V projection
    split_kernel<<<gAct, 256>>>(value, pAh, pAl, nAct);
    split_kernel<<<gW,   256>>>(Wv, pWh, pWl, nW);
    gemm_kernel<<<gGemm, 256, GSMEM>>>(pAh, pAl, pWh, pWl, bv, nullptr, pVh, pVl, 1.f, 1);

    // Wo split early (independent), then attention (writes split into pAh/pAl)
    split_kernel<<<gW, 256>>>(Wo, pWh, pWl, nW);
    attn_kernel<<<dim3(S_ / 128, H_, B_), 256, ASMEM>>>(pQh, pQl, pKh, pKl, pVh, pVl, pAh, pAl);

    // output projection (fp32 + bias)
    gemm_kernel<<<gGemm, 256, GSMEM>>>(pAh, pAl, pWh, pWl, bo, out, nullptr, nullptr, 1.f, 0);
}

// round 5
// speedup vs baseline: 5.5422x; 1.3394x over previous
#include <cuda_runtime.h>
#include <cuda_fp16.h>
#include <math.h>
#include <stdint.h>

#define B_  2
#define S_  2048
#define D_  768
#define H_  12
#define DK_ 64
#define M_  (B_*S_)   // 4096
#define MD_ (M_*D_)
#define DD_ (D_*D_)

// ---------------- scratch (__device__ globals; allocation-free rule) --------
__device__ __half g_Xh[3*MD_], g_Xl[3*MD_];   // activation splits (q,k,v inputs)
__device__ __half g_W2h[4*DD_], g_W2l[4*DD_]; // weight splits (Wq,Wk,Wv,Wo)
__device__ __half g_Qh[MD_], g_Ql[MD_];       // Q 2-plane (0.125 folded)
__device__ __half g_Kh[MD_];                  // K single plane
__device__ __half g_Vh[MD_];                  // V single plane
__device__ __half g_Co[MD_];                  // attention out, single plane

// ---------------- helpers ---------------------------------------------------
__device__ __forceinline__ uint32_t smem_u32(const void* p) {
    return (uint32_t)__cvta_generic_to_shared(p);
}
__device__ __forceinline__ void split_pack_h(float x0, float x1, uint32_t& hi, uint32_t& lo) {
    __half2 h = __floats2half2_rn(x0, x1);
    float h0 = __low2float(h), h1 = __high2float(h);
    __half2 l = __floats2half2_rn(x0 - h0, x1 - h1);
    hi = *reinterpret_cast<uint32_t*>(&h);
    lo = *reinterpret_cast<uint32_t*>(&l);
}
__device__ __forceinline__ uint32_t pack_h2(float x0, float x1) {
    __half2 h = __floats2half2_rn(x0, x1);
    return *reinterpret_cast<uint32_t*>(&h);
}
__device__ __forceinline__ void cp16(uint32_t dst, const void* src) {
    asm volatile("cp.async.cg.shared.global [%0], [%1], 16;\n" :: "r"(dst), "l"(src));
}
#define CP_COMMIT() asm volatile("cp.async.commit_group;\n" ::: "memory")
#define CP_WAIT0()  asm volatile("cp.async.wait_group 0;\n" ::: "memory")
#define CP_WAIT1()  asm volatile("cp.async.wait_group 1;\n" ::: "memory")

__device__ __forceinline__ void ldsm_x4(uint32_t& r0, uint32_t& r1, uint32_t& r2, uint32_t& r3, uint32_t addr) {
    asm volatile("ldmatrix.sync.aligned.m8n8.x4.shared.b16 {%0,%1,%2,%3}, [%4];\n"
                 : "=r"(r0), "=r"(r1), "=r"(r2), "=r"(r3) : "r"(addr));
}
__device__ __forceinline__ void ldsm_x4t(uint32_t& r0, uint32_t& r1, uint32_t& r2, uint32_t& r3, uint32_t addr) {
    asm volatile("ldmatrix.sync.aligned.m8n8.x4.trans.shared.b16 {%0,%1,%2,%3}, [%4];\n"
                 : "=r"(r0), "=r"(r1), "=r"(r2), "=r"(r3) : "r"(addr));
}
__device__ __forceinline__ void ldsm_x4a(uint32_t a[4], uint32_t addr) {
    ldsm_x4(a[0], a[1], a[2], a[3], addr);
}
__device__ __forceinline__ void mma_f16(float d[4], const uint32_t a[4], uint32_t b0, uint32_t b1) {
    asm volatile("mma.sync.aligned.m16n8k16.row.col.f32.f16.f16.f32 "
                 "{%0,%1,%2,%3}, {%4,%5,%6,%7}, {%8,%9}, {%0,%1,%2,%3};\n"
                 : "+f"(d[0]), "+f"(d[1]), "+f"(d[2]), "+f"(d[3])
                 : "r"(a[0]), "r"(a[1]), "r"(a[2]), "r"(a[3]), "r"(b0), "r"(b1));
}

// ---------------- merged input split: fp32 -> (hi, lo) fp16 -----------------
// grid.z in {0,1,2} selects q/k/v input; outputs at g_Xh/g_Xl + z*MD_
__global__ __launch_bounds__(256) void split_act_kernel(
    const float* __restrict__ q, const float* __restrict__ k,
    const float* __restrict__ v, __half* __restrict__ XH, __half* __restrict__ XL)
{
    const float* x = (blockIdx.z == 0) ? q : (blockIdx.z == 1) ? k : v;
    size_t base = (size_t)blockIdx.z * MD_;
    int i = (blockIdx.x * 256 + threadIdx.x) * 4;
    float4 val = *(const float4*)(x + i);
    uint32_t h01, h23, l01, l23;
    split_pack_h(val.x, val.y, h01, l01);
    split_pack_h(val.z, val.w, h23, l23);
    *(uint2*)(XH + base + i) = make_uint2(h01, h23);
    *(uint2*)(XL + base + i) = make_uint2(l01, l23);
}

// ---------------- merged weight split: grid.z in {0..3} ---------------------
__global__ __launch_bounds__(256) void split_w_kernel(
    const float* __restrict__ wq, const float* __restrict__ wk,
    const float* __restrict__ wv, const float* __restrict__ wo,
    __half* __restrict__ WH, __half* __restrict__ WL)
{
    const float* w = (blockIdx.z == 0) ? wq : (blockIdx.z == 1) ? wk
                   : (blockIdx.z == 2) ? wv : wo;
    size_t base = (size_t)blockIdx.z * DD_;
    int i = (blockIdx.x * 256 + threadIdx.x) * 4;
    float4 val = *(const float4*)(w + i);
    uint32_t h01, h23, l01, l23;
    split_pack_h(val.x, val.y, h01, l01);
    split_pack_h(val.z, val.w, h23, l23);
    *(uint2*)(WH + base + i) = make_uint2(h01, h23);
    *(uint2*)(WL + base + i) = make_uint2(l01, l23);
}

// ---------------- GEMM: C[4096,768] = A @ W + bias --------------------------
// fp16 split HMMA. BM=128 BN=64 BK=32; 256 thr (8 warps, 4x2), cp.async x2.
// terms: 3 = AhWh+AhWl+AlWh (QKV proj), 2 = AhWh+AhWl (O-proj, Al unused).
// mode: 0 fp32 out; 1 fp16 2-plane out (scaled); 2 fp16 1-plane out (scaled).
#define GA_H 0u
#define GA_L 10240u
#define GB_H 20480u
#define GB_L 25088u
#define GSTAGE 29696u
#define GSMEM (2 * GSTAGE)

__global__ __launch_bounds__(256) void gemm_kernel(
    const __half* __restrict__ Ah, const __half* __restrict__ Al,
    const __half* __restrict__ Wh, const __half* __restrict__ Wl,
    const float* __restrict__ bias,
    float* __restrict__ outF, __half* __restrict__ outH,
    __half* __restrict__ outL, float scale, int mode, int useAl)
{
    extern __shared__ char sm[];
    const int tid = threadIdx.x;
    const int lane = tid & 31, warp = tid >> 5;
    const int wm = warp & 3, wn = warp >> 2;
    const int row0 = blockIdx.y * 128, col0 = blockIdx.x * 64;
    const uint32_t sbase = smem_u32(sm);

    float acc[2][4][4] = {};

    auto load_stage = [&](int stage, int k0) {
        uint32_t st = sbase + stage * GSTAGE;
        #pragma unroll
        for (int i = 0; i < 2; i++) {
            int f = tid + i * 256;
            int r = f >> 2, c = f & 3;
            size_t g = (size_t)(row0 + r) * D_ + k0 + c * 8;
            cp16(st + GA_H + r * 80 + c * 16, Ah + g);
            if (useAl) cp16(st + GA_L + r * 80 + c * 16, Al + g);
        }
        {
            int r = tid >> 3, c = tid & 7;
            size_t g = (size_t)(k0 + r) * D_ + col0 + c * 8;
            cp16(st + GB_H + r * 144 + c * 16, Wh + g);
            cp16(st + GB_L + r * 144 + c * 16, Wl + g);
        }
        CP_COMMIT();
    };

    load_stage(0, 0);

    const int NCHUNK = D_ / 32;   // 24
    for (int chunk = 0; chunk < NCHUNK; chunk++) {
        if (chunk + 1 < NCHUNK) {
            load_stage((chunk + 1) & 1, (chunk + 1) * 32);
            CP_WAIT1();
        } else {
            CP_WAIT0();
        }
        __syncthreads();
        const uint32_t st = sbase + (chunk & 1) * GSTAGE;

        #pragma unroll
        for (int kk = 0; kk < 2; kk++) {
            uint32_t aF[2][2][4];
            #pragma unroll
            for (int mt = 0; mt < 2; mt++) {
                uint32_t off = (uint32_t)((wm * 32 + mt * 16 + (lane & 15)) * 80 + kk * 32 + (lane >> 4) * 16);
                ldsm_x4a(aF[0][mt], st + GA_H + off);
                if (useAl) ldsm_x4a(aF[1][mt], st + GA_L + off);
            }
            uint32_t bF[2][4][2];
            #pragma unroll
            for (int g = 0; g < 2; g++) {
                uint32_t off = (uint32_t)((kk * 16 + (lane & 15)) * 144 + (wn * 32 + g * 16) * 2 + (lane >> 4) * 16);
                uint32_t r0, r1, r2, r3;
                ldsm_x4t(r0, r1, r2, r3, st + GB_H + off);
                bF[0][2*g][0] = r0; bF[0][2*g][1] = r1; bF[0][2*g+1][0] = r2; bF[0][2*g+1][1] = r3;
                ldsm_x4t(r0, r1, r2, r3, st + GB_L + off);
                bF[1][2*g][0] = r0; bF[1][2*g][1] = r1; bF[1][2*g+1][0] = r2; bF[1][2*g+1][1] = r3;
            }
            #pragma unroll
            for (int mt = 0; mt < 2; mt++)
                #pragma unroll
                for (int nt = 0; nt < 4; nt++) {
                    mma_f16(acc[mt][nt], aF[0][mt], bF[0][nt][0], bF[0][nt][1]);
                    mma_f16(acc[mt][nt], aF[0][mt], bF[1][nt][0], bF[1][nt][1]);
                    if (useAl)
                        mma_f16(acc[mt][nt], aF[1][mt], bF[0][nt][0], bF[0][nt][1]);
                }
        }
        __syncthreads();
    }

    #pragma unroll
    for (int mt = 0; mt < 2; mt++)
        #pragma unroll
        for (int nt = 0; nt < 4; nt++) {
            int r = row0 + wm * 32 + mt * 16 + (lane >> 2);
            int c = col0 + wn * 32 + nt * 8 + (lane & 3) * 2;
            float b0 = bias[c], b1 = bias[c + 1];
            float v00 = acc[mt][nt][0] + b0, v01 = acc[mt][nt][1] + b1;
            float v10 = acc[mt][nt][2] + b0, v11 = acc[mt][nt][3] + b1;
            if (mode == 0) {
                outF[(size_t)r * D_ + c]           = v00;
                outF[(size_t)r * D_ + c + 1]       = v01;
                outF[(size_t)(r + 8) * D_ + c]     = v10;
                outF[(size_t)(r + 8) * D_ + c + 1] = v11;
            } else if (mode == 1) {
                uint32_t hh, ll;
                split_pack_h(v00 * scale, v01 * scale, hh, ll);
                *(uint32_t*)(outH + (size_t)r * D_ + c) = hh;
                *(uint32_t*)(outL + (size_t)r * D_ + c) = ll;
                split_pack_h(v10 * scale, v11 * scale, hh, ll);
                *(uint32_t*)(outH + (size_t)(r + 8) * D_ + c) = hh;
                *(uint32_t*)(outL + (size_t)(r + 8) * D_ + c) = ll;
            } else {
                *(uint32_t*)(outH + (size_t)r * D_ + c)       = pack_h2(v00 * scale, v01 * scale);
                *(uint32_t*)(outH + (size_t)(r + 8) * D_ + c) = pack_h2(v10 * scale, v11 * scale);
            }
        }
}

// ---------------- Flash attention (fp16: QK 2-term, PV 1-term) --------------
// Block: 256 thr (8 warps x m16 = 128 queries). KV tiles of 64 keys, 2-stage
// cp.async. Stage (18432 B): Kh@0, Vh@9216 (144B rows). Q 2-plane at 36864.
// Output: single fp16 plane (A-operand of O-projection).
#define AK_H 0u
#define AV_H 9216u
#define ASTAGE 18432u
#define AQ_OFF 36864u
#define ASMEM (2 * ASTAGE + 2 * 18432)

__global__ __launch_bounds__(256, 1) void attn_kernel(
    const __half* __restrict__ Qh, const __half* __restrict__ Ql,
    const __half* __restrict__ Kh, const __half* __restrict__ Vh,
    __half* __restrict__ O)
{
    extern __shared__ char smem[];
    const int tid = threadIdx.x;
    const int lane = tid & 31, w = tid >> 5;
    const int b = blockIdx.z, h = blockIdx.y;
    const int q0 = blockIdx.x * 128;
    const int headoff = h * DK_;
    const uint32_t sbase = smem_u32(smem);

    auto load_kv = [&](int stage, int t) {
        uint32_t st = sbase + stage * ASTAGE;
        #pragma unroll
        for (int i = 0; i < 2; i++) {
            int flat = tid + i * 256;
            int r = flat >> 3, c = flat & 7;
            size_t g = (size_t)(b * S_ + t + r) * D_ + headoff + c * 8;
            uint32_t o = (uint32_t)(r * 144 + c * 16);
            cp16(st + AK_H + o, Kh + g);
            cp16(st + AV_H + o, Vh + g);
        }
        CP_COMMIT();
    };

    // stage Q (2 planes) into Q area; prefetch KV tile 0 into stage 0
    #pragma unroll
    for (int i = 0; i < 4; i++) {
        int flat = tid + i * 256;
        int r = flat >> 3, c = flat & 7;
        size_t g = (size_t)(b * S_ + q0 + r) * D_ + headoff + c * 8;
        uint32_t o = (uint32_t)(r * 144 + c * 16);
        cp16(sbase + AQ_OFF + o, Qh + g);
        cp16(sbase + AQ_OFF + 18432 + o, Ql + g);
    }
    CP_COMMIT();
    load_kv(0, 0);
    CP_WAIT1();           // Q group complete
    __syncthreads();

    uint32_t qF[2][4][4];
    #pragma unroll
    for (int kt = 0; kt < 4; kt++) {
        uint32_t off = (uint32_t)((w * 16 + (lane & 15)) * 144 + kt * 32 + (lane >> 4) * 16);
        ldsm_x4a(qF[0][kt], sbase + AQ_OFF + off);
        ldsm_x4a(qF[1][kt], sbase + AQ_OFF + 18432 + off);
    }

    float Oacc[8][4] = {};
    float m0 = -1e30f, m1 = -1e30f, lsum0 = 0.f, lsum1 = 0.f;

    const int NT = S_ / 64;   // 32 tiles; tile ti in stage ti&1
    for (int ti = 0; ti < NT; ti++) {
        if (ti + 1 < NT) {
            load_kv((ti + 1) & 1, (ti + 1) * 64);
            CP_WAIT1();
        } else {
            CP_WAIT0();
        }
        __syncthreads();
        const uint32_t cur = sbase + (ti & 1) * ASTAGE;

        // ---- S = Q . K^T  (Q 2-term x K single plane) ----
        float sF[8][4] = {};
        #pragma unroll
        for (int kt = 0; kt < 4; kt++) {
            #pragma unroll
            for (int g = 0; g < 4; g++) {
                uint32_t off = (uint32_t)(((g << 4) + ((lane >> 4) << 3) + (lane & 7)) * 144
                                          + kt * 32 + ((lane >> 3) & 1) * 16);
                uint32_t bh0, bh1, bh2, bh3;
                ldsm_x4(bh0, bh1, bh2, bh3, cur + AK_H + off);
                mma_f16(sF[2*g],   qF[0][kt], bh0, bh1);
                mma_f16(sF[2*g],   qF[1][kt], bh0, bh1);
                mma_f16(sF[2*g+1], qF[0][kt], bh2, bh3);
                mma_f16(sF[2*g+1], qF[1][kt], bh2, bh3);
            }
        }

        // ---- online softmax ----
        float tm0 = -1e30f, tm1 = -1e30f;
        #pragma unroll
        for (int nt = 0; nt < 8; nt++) {
            tm0 = fmaxf(tm0, fmaxf(sF[nt][0], sF[nt][1]));
            tm1 = fmaxf(tm1, fmaxf(sF[nt][2], sF[nt][3]));
        }
        tm0 = fmaxf(tm0, __shfl_xor_sync(0xffffffffu, tm0, 1));
        tm0 = fmaxf(tm0, __shfl_xor_sync(0xffffffffu, tm0, 2));
        tm1 = fmaxf(tm1, __shfl_xor_sync(0xffffffffu, tm1, 1));
        tm1 = fmaxf(tm1, __shfl_xor_sync(0xffffffffu, tm1, 2));
        float mn0 = fmaxf(m0, tm0), mn1 = fmaxf(m1, tm1);
        float corr0 = __expf(m0 - mn0), corr1 = __expf(m1 - mn1);
        float rs0 = 0.f, rs1 = 0.f;
        #pragma unroll
        for (int nt = 0; nt < 8; nt++) {
            sF[nt][0] = __expf(sF[nt][0] - mn0);
            sF[nt][1] = __expf(sF[nt][1] - mn0);
            sF[nt][2] = __expf(sF[nt][2] - mn1);
            sF[nt][3] = __expf(sF[nt][3] - mn1);
            rs0 += sF[nt][0] + sF[nt][1];
            rs1 += sF[nt][2] + sF[nt][3];
        }
        rs0 += __shfl_xor_sync(0xffffffffu, rs0, 1);
        rs0 += __shfl_xor_sync(0xffffffffu, rs0, 2);
        rs1 += __shfl_xor_sync(0xffffffffu, rs1, 1);
        rs1 += __shfl_xor_sync(0xffffffffu, rs1, 2);
        lsum0 = lsum0 * corr0 + rs0;  m0 = mn0;
        lsum1 = lsum1 * corr1 + rs1;  m1 = mn1;
        #pragma unroll
        for (int nt = 0; nt < 8; nt++) {
            Oacc[nt][0] *= corr0; Oacc[nt][1] *= corr0;
            Oacc[nt][2] *= corr1; Oacc[nt][3] *= corr1;
        }

        // ---- O += P . V  (P single fp16, V single plane) ----
        #pragma unroll
        for (int kt = 0; kt < 4; kt++) {
            uint32_t aH[4];
            aH[0] = pack_h2(sF[2*kt][0],   sF[2*kt][1]);
            aH[1] = pack_h2(sF[2*kt][2],   sF[2*kt][3]);
            aH[2] = pack_h2(sF[2*kt+1][0], sF[2*kt+1][1]);
            aH[3] = pack_h2(sF[2*kt+1][2], sF[2*kt+1][3]);
            #pragma unroll
            for (int g = 0; g < 4; g++) {
                uint32_t off = (uint32_t)((kt * 16 + (lane & 15)) * 144 + g * 32 + (lane >> 4) * 16);
                uint32_t vh0, vh1, vh2, vh3;
                ldsm_x4t(vh0, vh1, vh2, vh3, cur + AV_H + off);
                mma_f16(Oacc[2*g],   aH, vh0, vh1);
                mma_f16(Oacc[2*g+1], aH, vh2, vh3);
            }
        }
        __syncthreads();
    }

    const float inv0 = 1.f / lsum0, inv1 = 1.f / lsum1;
    const int r = q0 + w * 16 + (lane >> 2);
    #pragma unroll
    for (int nt = 0; nt < 8; nt++) {
        int c = headoff + nt * 8 + (lane & 3) * 2;
        size_t o0 = (size_t)(b * S_ + r) * D_ + c;
        size_t o1 = o0 + (size_t)8 * D_;
        *(uint32_t*)(O + o0) = pack_h2(Oacc[nt][0] * inv0, Oacc[nt][1] * inv0);
        *(uint32_t*)(O + o1) = pack_h2(Oacc[nt][2] * inv1, Oacc[nt][3] * inv1);
    }
}

// ---------------------------------------------------------------------------
extern "C" void kernel_launch(void* const* d_in, const int* in_sizes, int n_in,
                              void* d_out, int out_size)
{
    const float* query = (const float*)d_in[0];
    const float* key   = (const float*)d_in[1];
    const float* value = (const float*)d_in[2];
    const float* Wq    = (const float*)d_in[3];
    const float* bq    = (const float*)d_in[4];
    const float* Wk    = (const float*)d_in[5];
    const float* bk    = (const float*)d_in[6];
    const float* Wv    = (const float*)d_in[7];
    const float* bv    = (const float*)d_in[8];
    const float* Wo    = (const float*)d_in[9];
    const float* bo    = (const float*)d_in[10];
    float* out = (float*)d_out;

    __half *pXh, *pXl, *pWh, *pWl, *pQh, *pQl, *pKh, *pVh, *pCo;
    cudaGetSymbolAddress((void**)&pXh, g_Xh);  cudaGetSymbolAddress((void**)&pXl, g_Xl);
    cudaGetSymbolAddress((void**)&pWh, g_W2h); cudaGetSymbolAddress((void**)&pWl, g_W2l);
    cudaGetSymbolAddress((void**)&pQh, g_Qh);  cudaGetSymbolAddress((void**)&pQl, g_Ql);
    cudaGetSymbolAddress((void**)&pKh, g_Kh);  cudaGetSymbolAddress((void**)&pVh, g_Vh);
    cudaGetSymbolAddress((void**)&pCo, g_Co);

    cudaFuncSetAttribute(gemm_kernel, cudaFuncAttributeMaxDynamicSharedMemorySize, GSMEM);
    cudaFuncSetAttribute(attn_kernel, cudaFuncAttributeMaxDynamicSharedMemorySize, ASMEM);

    dim3 gActS(MD_ / 4 / 256, 1, 3);   // (3072,1,3)
    dim3 gWS(DD_ / 4 / 256, 1, 4);     // (576,1,4)
    dim3 gGemm(D_ / 64, M_ / 128);     // (12, 32)

    split_act_kernel<<<gActS, 256>>>(query, key, value, pXh, pXl);
    split_w_kernel<<<gWS, 256>>>(Wq, Wk, Wv, Wo, pWh, pWl);

    // Q projection: 3 terms, fp16 2-plane out, 0.125 folded
    gemm_kernel<<<gGemm, 256, GSMEM>>>(pXh, pXl, pWh, pWl, bq,
                                       nullptr, pQh, pQl, 0.125f, 1, 1);
    // K projection: 3 terms, fp16 1-plane out
    gemm_kernel<<<gGemm, 256, GSMEM>>>(pXh + MD_, pXl + MD_, pWh + DD_, pWl + DD_, bk,
                                       nullptr, pKh, nullptr, 1.f, 2, 1);
    // V projection: 3 terms, fp16 1-plane out
    gemm_kernel<<<gGemm, 256, GSMEM>>>(pXh + 2*MD_, pXl + 2*MD_, pWh + 2*DD_, pWl + 2*DD_, bv,
                                       nullptr, pVh, nullptr, 1.f, 2, 1);

    // attention: QK 2-term, PV 1-term; writes single fp16 plane
    attn_kernel<<<dim3(S_ / 128, H_, B_), 256, ASMEM>>>(pQh, pQl, pKh, pVh, pCo);

    // output projection: 2 terms (Co x Wo_hi + Co x Wo_lo), fp32 out + bias
    gemm_kernel<<<gGemm, 256, GSMEM>>>(pCo, nullptr, pWh + 3*DD_, pWl + 3*DD_, bo,
                                       out, nullptr, nullptr, 1.f, 0, 0);
}